// round 2
// baseline (speedup 1.0000x reference)
#include <cuda_runtime.h>
#include <cstdint>

#define NEG   (-1e30f)
#define LOG2E (1.4426950408889634f)
#define LN2   (0.6931471805599453f)

// Fixed problem shape (B=32, T=1024, V=1000, L=128); scratch sized to max.
#define MAXB 32
#define MAXT 1024
#define MAXL 128
#define ESTR 132   // padded emission row stride (floats): 129 used

// Static scratch (no allocation allowed anywhere).
__device__ float g_emit[(size_t)MAXB * MAXT * ESTR];
__device__ float g_res[MAXB];

__device__ __forceinline__ float lse3_2(float a, float b, float c) {
    // logsumexp in log2 domain: m + log2(2^(a-m)+2^(b-m)+2^(c-m))
    float m = fmaxf(a, fmaxf(b, c));
    float s = exp2f(a - m) + exp2f(b - m) + exp2f(c - m);
    return m + __log2f(s);
}

// ---------------------------------------------------------------------------
// Kernel A: per (b,t) row — log-softmax denominator (log2 domain) + gather the
// 129 needed emissions (blank + L labels) into g_emit.
// One block of 128 threads per row; row values kept in registers (single pass).
// ---------------------------------------------------------------------------
__global__ void __launch_bounds__(128) lse_gather_kernel(
    const float* __restrict__ pred,
    const int*   __restrict__ target,
    int T, int V, int L)
{
    const int r = blockIdx.x;          // r = b*T + t
    const int b = r / T;
    const int tid = threadIdx.x;
    const int lane = tid & 31;
    const int wid = tid >> 5;

    const float* __restrict__ row = pred + (size_t)r * V;
    const float4* __restrict__ row4 = (const float4*)row;
    const int nvec = V >> 2;           // V divisible by 4 (1000 -> 250)

    // Each thread holds up to 2 float4 (covers V <= 1024 with 128 threads)
    const int i0 = tid, i1 = tid + 128;
    float4 va = make_float4(NEG, NEG, NEG, NEG);
    float4 vb = make_float4(NEG, NEG, NEG, NEG);
    const bool ha = (i0 < nvec), hb = (i1 < nvec);
    if (ha) va = row4[i0];
    if (hb) vb = row4[i1];

    float m = NEG;
    m = fmaxf(m, fmaxf(fmaxf(va.x, va.y), fmaxf(va.z, va.w)));
    m = fmaxf(m, fmaxf(fmaxf(vb.x, vb.y), fmaxf(vb.z, vb.w)));
    #pragma unroll
    for (int o = 16; o > 0; o >>= 1) m = fmaxf(m, __shfl_xor_sync(0xffffffffu, m, o));

    __shared__ float sred[4];
    __shared__ float s_lse;
    if (lane == 0) sred[wid] = m;
    __syncthreads();
    m = fmaxf(fmaxf(sred[0], sred[1]), fmaxf(sred[2], sred[3]));

    float sum = 0.f;
    if (ha) {
        sum += exp2f((va.x - m) * LOG2E) + exp2f((va.y - m) * LOG2E)
             + exp2f((va.z - m) * LOG2E) + exp2f((va.w - m) * LOG2E);
    }
    if (hb) {
        sum += exp2f((vb.x - m) * LOG2E) + exp2f((vb.y - m) * LOG2E)
             + exp2f((vb.z - m) * LOG2E) + exp2f((vb.w - m) * LOG2E);
    }
    #pragma unroll
    for (int o = 16; o > 0; o >>= 1) sum += __shfl_xor_sync(0xffffffffu, sum, o);
    __syncthreads();          // reuse sred
    if (lane == 0) sred[wid] = sum;
    __syncthreads();
    if (tid == 0) {
        float S = sred[0] + sred[1] + sred[2] + sred[3];
        s_lse = m * LOG2E + __log2f(S);   // log2(sum_v exp(x_v))
    }
    __syncthreads();
    const float lse2 = s_lse;

    // Gather: j=0 -> blank(0); j=1..L -> target[b][j-1]. Emission in log2.
    float* __restrict__ erow = g_emit + (size_t)r * ESTR;
    const int* __restrict__ tgt = target + (size_t)b * L;
    for (int j = tid; j <= L; j += blockDim.x) {
        int tok = (j == 0) ? 0 : tgt[j - 1];
        erow[j] = row[tok] * LOG2E - lse2;
    }
}

// ---------------------------------------------------------------------------
// Kernel B: W-CTC forward DP, one block per batch, one thread per state.
// Log2-domain; shared double buffer with 2-slot NEG sentinel prefix; one
// __syncthreads per time step. endstar tracked by thread 0.
// ---------------------------------------------------------------------------
__global__ void __launch_bounds__(288) wctc_dp_kernel(
    const int* __restrict__ target,
    const int* __restrict__ tlen,
    int T, int L)
{
    const int b = blockIdx.x;
    const int tid = threadIdx.x;
    const int S = 2 * L + 2;                 // 258

    __shared__ float buf[2][2 * MAXL + 4];   // [2][260]; idx s+2, [0..1] = NEG
    __shared__ int   tg[MAXL];

    for (int i = tid; i < L; i += blockDim.x) tg[i] = target[(size_t)b * L + i];
    if (tid < 2) { buf[0][tid] = NEG; buf[1][tid] = NEG; }
    __syncthreads();

    const int  tl      = tlen[b];
    const int  s       = tid;
    const bool active  = (s < S);
    const bool isStar  = (s == 0);
    const bool isBlank = ((s & 1) == 1);
    const bool isLab   = active && !isStar && !isBlank;
    const int  lab     = (s - 2) >> 1;                 // valid when isLab
    const int  j       = isLab ? (lab + 1) : 0;        // emission index
    const bool skipOK  = isLab && ((s == 2) || (tg[lab] != tg[lab - 1]));
    const bool validS  = (s <= 2 * tl + 1);
    const int  ll = 2 * tl, lb = ll + 1;

    const float* __restrict__ erow = g_emit + (size_t)b * T * ESTR;

    // t = 0
    if (active) {
        float a0 = NEG;
        if (s == 0)      a0 = 0.f;
        else if (s == 1) a0 = erow[0];
        else if (s == 2) a0 = erow[1];
        if (!validS)     a0 = NEG;
        buf[0][s + 2] = a0;
    }
    float endstar = NEG;   // meaningful in thread 0 only
    __syncthreads();

    int cur = 0;
    for (int t = 1; t < T; ++t) {
        const float* __restrict__ e = erow + (size_t)t * ESTR;
        float* C  = buf[cur];
        float* Nx = buf[cur ^ 1];
        if (tid == 0)
            endstar = lse3_2(endstar, C[ll + 2], C[lb + 2]);
        if (active) {
            float a  = C[s + 2];
            float p1 = C[s + 1];
            float p2 = skipOK ? C[s] : NEG;
            float r  = lse3_2(a, p1, p2);
            float ev = isStar ? 0.f : e[j];
            Nx[s + 2] = validS ? (ev + r) : NEG;
        }
        __syncthreads();
        cur ^= 1;
    }

    if (tid == 0) {
        float* C = buf[cur];
        float tot2 = lse3_2(C[ll + 2], C[lb + 2], endstar);  // log2 total
        g_res[b] = (-tot2 * LN2) / (float)tl;                // nll / target_length
    }
}

// ---------------------------------------------------------------------------
// Kernel C: mean over batch -> scalar output.
// ---------------------------------------------------------------------------
__global__ void __launch_bounds__(32) finalize_kernel(float* __restrict__ out, int B)
{
    float v = 0.f;
    for (int i = threadIdx.x; i < B; i += 32) v += g_res[i];
    #pragma unroll
    for (int o = 16; o > 0; o >>= 1) v += __shfl_xor_sync(0xffffffffu, v, o);
    if (threadIdx.x == 0) out[0] = v / (float)B;
}

extern "C" void kernel_launch(void* const* d_in, const int* in_sizes, int n_in,
                              void* d_out, int out_size)
{
    const float* pred   = (const float*)d_in[0];   // (B,T,V) fp32
    const int*   target = (const int*)d_in[1];     // (B,L)  int32
    const int*   tlen   = (const int*)d_in[2];     // (B,)   int32

    const int B = in_sizes[2];
    const int L = in_sizes[1] / B;
    const int V = 1000;
    const int T = in_sizes[0] / (B * V);

    lse_gather_kernel<<<B * T, 128>>>(pred, target, T, V, L);
    wctc_dp_kernel<<<B, 288>>>(target, tlen, T, L);
    finalize_kernel<<<1, 32>>>((float*)d_out, B);
}

// round 3
// speedup vs baseline: 1.8685x; 1.8685x over previous
#include <cuda_runtime.h>
#include <cstdint>

#define NEG   (-1e30f)
#define LOG2E (1.4426950408889634f)
#define LN2   (0.6931471805599453f)

// Fixed problem shape (B=32, T=1024, V=1000, L=128); scratch sized to max.
#define MAXB 32
#define MAXT 1024
#define MAXL 128
#define ESTR 132   // padded emission row stride (floats): 129 used

// Static scratch (no allocation allowed anywhere).
__device__ float g_emit[(size_t)MAXB * MAXT * ESTR];
__device__ float g_res[MAXB];

__device__ __forceinline__ float lse3_2(float a, float b, float c) {
    // logsumexp in log2 domain: m + log2(2^(a-m)+2^(b-m)+2^(c-m))
    float m = fmaxf(a, fmaxf(b, c));
    float s = exp2f(a - m) + exp2f(b - m) + exp2f(c - m);
    return m + __log2f(s);
}

// ---------------------------------------------------------------------------
// Kernel A: one WARP per (b,t) row. Single pass over V=1000 held in registers
// (8 float4 per lane); warp-shuffle max + sum reductions only (no shared, no
// __syncthreads). Emits log2-domain log-softmax for the 129 needed tokens.
// ---------------------------------------------------------------------------
__global__ void __launch_bounds__(128) lse_gather_kernel(
    const float* __restrict__ pred,
    const int*   __restrict__ target,
    int T, int V, int L, int nrows)
{
    const int warp = blockIdx.x * (blockDim.x >> 5) + (threadIdx.x >> 5);
    if (warp >= nrows) return;
    const int lane = threadIdx.x & 31;
    const int b = warp / T;

    const float* __restrict__ row = pred + (size_t)warp * V;
    const float4* __restrict__ row4 = (const float4*)row;
    const int nvec = V >> 2;     // 250

    float4 v[8];
    #pragma unroll
    for (int i = 0; i < 8; ++i) {
        const int idx = lane + (i << 5);
        v[i] = (idx < nvec) ? row4[idx] : make_float4(NEG, NEG, NEG, NEG);
    }

    float m = NEG;
    #pragma unroll
    for (int i = 0; i < 8; ++i)
        m = fmaxf(m, fmaxf(fmaxf(v[i].x, v[i].y), fmaxf(v[i].z, v[i].w)));
    #pragma unroll
    for (int o = 16; o > 0; o >>= 1) m = fmaxf(m, __shfl_xor_sync(0xffffffffu, m, o));

    const float m2 = m * LOG2E;
    float sum = 0.f;
    #pragma unroll
    for (int i = 0; i < 8; ++i) {
        sum += exp2f(fmaf(v[i].x, LOG2E, -m2)) + exp2f(fmaf(v[i].y, LOG2E, -m2))
             + exp2f(fmaf(v[i].z, LOG2E, -m2)) + exp2f(fmaf(v[i].w, LOG2E, -m2));
    }
    #pragma unroll
    for (int o = 16; o > 0; o >>= 1) sum += __shfl_xor_sync(0xffffffffu, sum, o);

    const float lse2 = m2 + __log2f(sum);   // log2(sum_v exp(x_v))

    // Gather: j=0 -> blank(0); j=1..L -> target[b][j-1]. Emission in log2.
    float* __restrict__ erow = g_emit + (size_t)warp * ESTR;
    const int* __restrict__ tgt = target + (size_t)b * L;
    for (int j = lane; j <= L; j += 32) {
        const int tok = (j == 0) ? 0 : tgt[j - 1];
        erow[j] = fmaf(row[tok], LOG2E, -lse2);
    }
}

// ---------------------------------------------------------------------------
// Kernel B: W-CTC forward DP, one block per batch, one thread per state.
// Log2-domain; shared double buffer; ONE __syncthreads per step.
// Emissions prefetched 2 steps ahead into a register queue so the global-load
// latency (L2 ~250cyc) is hidden behind two iterations of compute+barrier.
// ---------------------------------------------------------------------------
__global__ void __launch_bounds__(288) wctc_dp_kernel(
    const int* __restrict__ target,
    const int* __restrict__ tlen,
    int T, int L)
{
    const int b = blockIdx.x;
    const int tid = threadIdx.x;
    const int S = 2 * L + 2;                 // 258

    __shared__ float buf[2][2 * MAXL + 4];   // [2][260]; idx s+2, [0..1] = NEG
    __shared__ int   tg[MAXL];

    for (int i = tid; i < L; i += blockDim.x) tg[i] = target[(size_t)b * L + i];
    if (tid < 2) { buf[0][tid] = NEG; buf[1][tid] = NEG; }
    __syncthreads();

    const int  tl      = tlen[b];
    const int  s       = tid;
    const bool active  = (s < S);
    const bool isStar  = (s == 0);
    const bool isBlank = ((s & 1) == 1);
    const bool isLab   = active && !isStar && !isBlank;
    const int  lab     = isLab ? ((s - 2) >> 1) : 0;
    const int  jj      = isLab ? (lab + 1) : 0;        // emission index (star ignores)
    const bool skipOK  = isLab && ((s == 2) || (tg[lab] != tg[lab - 1]));
    const bool validS  = (s <= 2 * tl + 1);
    const int  ll = 2 * tl, lb = ll + 1;

    const float* __restrict__ erow = g_emit + (size_t)b * T * ESTR;

    // t = 0
    if (active) {
        float a0 = NEG;
        if (s == 0)      a0 = 0.f;
        else if (s == 1) a0 = erow[0];
        else if (s == 2) a0 = erow[1];
        if (!validS)     a0 = NEG;
        buf[0][s + 2] = a0;
    }
    float endstar = NEG;   // meaningful in thread 0 only

    // Prefetch queue: ev0 = emission(t=1), ev1 = emission(t=2)
    float ev0 = 0.f, ev1 = 0.f;
    if (active) {
        ev0 = erow[(size_t)1 * ESTR + jj];
        if (T > 2) ev1 = erow[(size_t)2 * ESTR + jj];
    }
    __syncthreads();

    int cur = 0;
    #pragma unroll 2
    for (int t = 1; t < T; ++t) {
        // Issue next prefetch FIRST so it overlaps ~2 iterations of compute.
        float evn = 0.f;
        if (active && (t + 2 < T)) evn = erow[(size_t)(t + 2) * ESTR + jj];

        float* C  = buf[cur];
        float* Nx = buf[cur ^ 1];
        if (tid == 0)
            endstar = lse3_2(endstar, C[ll + 2], C[lb + 2]);
        if (active) {
            float a  = C[s + 2];
            float p1 = C[s + 1];
            float p2 = skipOK ? C[s] : NEG;
            float r  = lse3_2(a, p1, p2);
            float ev = isStar ? 0.f : ev0;
            Nx[s + 2] = validS ? (ev + r) : NEG;
        }
        ev0 = ev1; ev1 = evn;
        __syncthreads();
        cur ^= 1;
    }

    if (tid == 0) {
        float* C = buf[cur];
        float tot2 = lse3_2(C[ll + 2], C[lb + 2], endstar);  // log2 total
        g_res[b] = (-tot2 * LN2) / (float)tl;                // nll / target_length
    }
}

// ---------------------------------------------------------------------------
// Kernel C: mean over batch -> scalar output.
// ---------------------------------------------------------------------------
__global__ void __launch_bounds__(32) finalize_kernel(float* __restrict__ out, int B)
{
    float v = 0.f;
    for (int i = threadIdx.x; i < B; i += 32) v += g_res[i];
    #pragma unroll
    for (int o = 16; o > 0; o >>= 1) v += __shfl_xor_sync(0xffffffffu, v, o);
    if (threadIdx.x == 0) out[0] = v / (float)B;
}

extern "C" void kernel_launch(void* const* d_in, const int* in_sizes, int n_in,
                              void* d_out, int out_size)
{
    const float* pred   = (const float*)d_in[0];   // (B,T,V) fp32
    const int*   target = (const int*)d_in[1];     // (B,L)  int32
    const int*   tlen   = (const int*)d_in[2];     // (B,)   int32

    const int B = in_sizes[2];
    const int L = in_sizes[1] / B;
    const int V = 1000;
    const int T = in_sizes[0] / (B * V);
    const int nrows = B * T;

    // 4 warps per block, one warp per (b,t) row
    lse_gather_kernel<<<(nrows + 3) / 4, 128>>>(pred, target, T, V, L, nrows);
    wctc_dp_kernel<<<B, 288>>>(target, tlen, T, L);
    finalize_kernel<<<1, 32>>>((float*)d_out, B);
}